// round 14
// baseline (speedup 1.0000x reference)
#include <cuda_runtime.h>

#define H 128
#define MAXN 100000
#define MAXE 1600000
#define TPB 384
#define WARPS 12
#define NP_L 3
#define RPL 6
#define NP_UV 3
#define RPUV 6

// ---------------- scratch (device globals; no allocations anywhere) ----------------
__device__ __align__(128) float g_mean[MAXN * H];
__device__ __align__(128) float g_x1[MAXN * H];
__device__ __align__(128) float g_x2[MAXN * H];
__device__ __align__(128) float g_u[MAXN * H];
__device__ __align__(128) float g_v[MAXN * H];
__device__ __align__(128) int g_cnt[MAXN];
__device__ __align__(128) int g_off[MAXN + 1];
__device__ __align__(128) int g_cur[MAXN];
__device__ __align__(128) int g_bsum[128];
__device__ __align__(128) int g_csr[MAXE];

typedef unsigned long long u64;

static __device__ __forceinline__ u64 pk2(float a, float b) {
    u64 r;
    asm("mov.b64 %0, {%1,%2};" : "=l"(r) : "f"(a), "f"(b));
    return r;
}
static __device__ __forceinline__ void fma2(u64& d, u64 a, u64 b) {
    asm("fma.rn.f32x2 %0, %1, %2, %0;" : "+l"(d) : "l"(a), "l"(b));
}
static __device__ __forceinline__ float2 upk(u64 a) {
    float2 r;
    asm("mov.b64 {%0,%1}, %2;" : "=f"(r.x), "=f"(r.y) : "l"(a));
    return r;
}

// ---------------- CSR construction ----------------
__global__ void zeroi_kernel(int* p, int n) {
    int i = blockIdx.x * blockDim.x + threadIdx.x;
    if (i < n) p[i] = 0;
}
__global__ void hist_kernel(const int* __restrict__ dst, int* __restrict__ cnt, int nE) {
    int i = blockIdx.x * blockDim.x + threadIdx.x;
    int stride = gridDim.x * blockDim.x;
    for (int e = i; e < nE; e += stride) atomicAdd(cnt + dst[e], 1);
}
__global__ void scan1_kernel(const int* __restrict__ cnt, int* __restrict__ off,
                             int* __restrict__ bsum, int n) {
    __shared__ int sm[1024];
    int i = blockIdx.x * 1024 + threadIdx.x;
    int v = (i < n) ? cnt[i] : 0;
    sm[threadIdx.x] = v;
    __syncthreads();
    for (int d = 1; d < 1024; d <<= 1) {
        int t = (threadIdx.x >= d) ? sm[threadIdx.x - d] : 0;
        __syncthreads();
        sm[threadIdx.x] += t;
        __syncthreads();
    }
    if (i < n) off[i] = sm[threadIdx.x] - v;  // exclusive
    if (threadIdx.x == 1023) bsum[blockIdx.x] = sm[1023];
}
__global__ void scan2_kernel(int* bsum, int nb) {
    __shared__ int sm[128];
    int v = (threadIdx.x < nb) ? bsum[threadIdx.x] : 0;
    sm[threadIdx.x] = v;
    __syncthreads();
    for (int d = 1; d < 128; d <<= 1) {
        int t = (threadIdx.x >= d) ? sm[threadIdx.x - d] : 0;
        __syncthreads();
        sm[threadIdx.x] += t;
        __syncthreads();
    }
    if (threadIdx.x < nb) bsum[threadIdx.x] = sm[threadIdx.x] - v;  // exclusive
}
__global__ void scan3_kernel(int* __restrict__ off, const int* __restrict__ bsum,
                             int* __restrict__ cur, int n, int nE) {
    int i = blockIdx.x * blockDim.x + threadIdx.x;
    if (i < n) {
        int o = off[i] + bsum[i >> 10];
        off[i] = o;
        cur[i] = o;
    }
    if (i == 0) off[n] = nE;
}
__global__ void fill_kernel(const int* __restrict__ src, const int* __restrict__ dst,
                            int* __restrict__ cur, int* __restrict__ csr, int nE) {
    int i = blockIdx.x * blockDim.x + threadIdx.x;
    int stride = gridDim.x * blockDim.x;
    for (int e = i; e < nE; e += stride) {
        int pos = atomicAdd(cur + dst[e], 1);
        csr[pos] = src[e];
    }
}

// ---------------- gather-aggregate: mean[node] = sum_{src in N(node)} x[src] / max(deg,1) ----------------
__global__ void gather_kernel(const float* __restrict__ x, const int* __restrict__ csr,
                              const int* __restrict__ off, float* __restrict__ mean, int n) {
    int w = (blockIdx.x * blockDim.x + threadIdx.x) >> 5;
    if (w >= n) return;
    int lane = threadIdx.x & 31;
    int c0 = lane * 4;
    int e0 = off[w], e1 = off[w + 1];
    float4 a0 = make_float4(0.f, 0.f, 0.f, 0.f), a1 = a0, a2 = a0, a3 = a0;
    int e = e0;
    for (; e + 4 <= e1; e += 4) {
        int i0 = csr[e], i1 = csr[e + 1], i2 = csr[e + 2], i3 = csr[e + 3];
        float4 v0 = *(const float4*)(x + (size_t)i0 * H + c0);
        float4 v1 = *(const float4*)(x + (size_t)i1 * H + c0);
        float4 v2 = *(const float4*)(x + (size_t)i2 * H + c0);
        float4 v3 = *(const float4*)(x + (size_t)i3 * H + c0);
        a0.x += v0.x; a0.y += v0.y; a0.z += v0.z; a0.w += v0.w;
        a1.x += v1.x; a1.y += v1.y; a1.z += v1.z; a1.w += v1.w;
        a2.x += v2.x; a2.y += v2.y; a2.z += v2.z; a2.w += v2.w;
        a3.x += v3.x; a3.y += v3.y; a3.z += v3.z; a3.w += v3.w;
    }
    for (; e < e1; e++) {
        int i0 = csr[e];
        float4 v0 = *(const float4*)(x + (size_t)i0 * H + c0);
        a0.x += v0.x; a0.y += v0.y; a0.z += v0.z; a0.w += v0.w;
    }
    float rd = 1.0f / fmaxf((float)(e1 - e0), 1.0f);
    float4 acc;
    acc.x = (a0.x + a1.x + a2.x + a3.x) * rd;
    acc.y = (a0.y + a1.y + a2.y + a3.y) * rd;
    acc.z = (a0.z + a1.z + a2.z + a3.z) * rd;
    acc.w = (a0.w + a1.w + a2.w + a3.w) * rd;
    *(float4*)(mean + (size_t)w * H + c0) = acc;
}

// ---------------- fused SAGE layer, software-pipelined ----------------
// out = relu(mean@Wl + x@Wr + b). Row-pair f32x2 compute (R7) with register
// double-buffering: stage prefetched tile -> issue next tile's LDGs -> compute.
__global__ void __launch_bounds__(TPB, 1)
layer_kernel(const float* __restrict__ x, const float* __restrict__ mean,
             const float* __restrict__ Wl, const float* __restrict__ Wr,
             const float* __restrict__ bias, float* __restrict__ out, int n) {
    extern __shared__ float sm[];
    float* Ws = sm;                           // 256*128 floats = 128KB
    float2* stage = (float2*)(sm + 256 * H);  // WARPS * NP_L * 256 float2 = 72KB
    for (int i = threadIdx.x; i < H * H; i += TPB) {
        Ws[i] = Wl[i];
        Ws[H * H + i] = Wr[i];
    }
    __syncthreads();
    const int warp = threadIdx.x >> 5, lane = threadIdx.x & 31;
    const int c0 = lane * 4;
    float2* st = stage + warp * (NP_L * 256);
    const float4 b4 = *(const float4*)(bias + c0);
    const int stride = gridDim.x * (WARPS * RPL);
    int base = blockIdx.x * (WARPS * RPL) + warp * RPL;

    float4 pm0[NP_L], pm1[NP_L], px0[NP_L], px1[NP_L];
    const float4 z4 = make_float4(0.f, 0.f, 0.f, 0.f);
    if (base < n) {
#pragma unroll
        for (int rp = 0; rp < NP_L; rp++) {
            int r0 = base + 2 * rp, r1 = r0 + 1;
            pm0[rp] = z4; pm1[rp] = z4; px0[rp] = z4; px1[rp] = z4;
            if (r0 < n) {
                pm0[rp] = *(const float4*)(mean + (size_t)r0 * H + c0);
                px0[rp] = *(const float4*)(x + (size_t)r0 * H + c0);
            }
            if (r1 < n) {
                pm1[rp] = *(const float4*)(mean + (size_t)r1 * H + c0);
                px1[rp] = *(const float4*)(x + (size_t)r1 * H + c0);
            }
        }
    }

    for (; base < n; base += stride) {
        // ---- stage prefetched tile (row-pair interleave) ----
#pragma unroll
        for (int rp = 0; rp < NP_L; rp++) {
            float2* b = st + rp * 256;
            *(float4*)(b + c0) = make_float4(pm0[rp].x, pm1[rp].x, pm0[rp].y, pm1[rp].y);
            *(float4*)(b + c0 + 2) = make_float4(pm0[rp].z, pm1[rp].z, pm0[rp].w, pm1[rp].w);
            *(float4*)(b + 128 + c0) = make_float4(px0[rp].x, px1[rp].x, px0[rp].y, px1[rp].y);
            *(float4*)(b + 128 + c0 + 2) =
                make_float4(px0[rp].z, px1[rp].z, px0[rp].w, px1[rp].w);
        }
        __syncwarp();

        // ---- prefetch NEXT tile (LDGs in flight during compute) ----
        int nb = base + stride;
        if (nb < n) {
#pragma unroll
            for (int rp = 0; rp < NP_L; rp++) {
                int r0 = nb + 2 * rp, r1 = r0 + 1;
                pm0[rp] = z4; pm1[rp] = z4; px0[rp] = z4; px1[rp] = z4;
                if (r0 < n) {
                    pm0[rp] = *(const float4*)(mean + (size_t)r0 * H + c0);
                    px0[rp] = *(const float4*)(x + (size_t)r0 * H + c0);
                }
                if (r1 < n) {
                    pm1[rp] = *(const float4*)(mean + (size_t)r1 * H + c0);
                    px1[rp] = *(const float4*)(x + (size_t)r1 * H + c0);
                }
            }
        }

        // ---- compute current tile ----
        u64 acc[NP_L][4];
#pragma unroll
        for (int rp = 0; rp < NP_L; rp++)
#pragma unroll
            for (int c = 0; c < 4; c++) acc[rp][c] = 0ull;

#pragma unroll 2
        for (int k4 = 0; k4 < 64; k4++) {
            ulonglong2 ap0[NP_L], ap1[NP_L];
#pragma unroll
            for (int rp = 0; rp < NP_L; rp++) {
                const float2* b = st + rp * 256 + 4 * k4;
                ap0[rp] = *(const ulonglong2*)(b);
                ap1[rp] = *(const ulonglong2*)(b + 2);
            }
#pragma unroll
            for (int j = 0; j < 4; j++) {
                float4 w = *(const float4*)(Ws + (4 * k4 + j) * H + c0);
                u64 wa = pk2(w.x, w.x), wb = pk2(w.y, w.y);
                u64 wc = pk2(w.z, w.z), wd = pk2(w.w, w.w);
#pragma unroll
                for (int rp = 0; rp < NP_L; rp++) {
                    u64 a = (j == 0) ? ap0[rp].x : (j == 1) ? ap0[rp].y
                                                 : (j == 2) ? ap1[rp].x : ap1[rp].y;
                    fma2(acc[rp][0], wa, a);
                    fma2(acc[rp][1], wb, a);
                    fma2(acc[rp][2], wc, a);
                    fma2(acc[rp][3], wd, a);
                }
            }
        }

        // ---- epilogue ----
#pragma unroll
        for (int rp = 0; rp < NP_L; rp++) {
            int r0 = base + 2 * rp, r1 = r0 + 1;
            float2 v0 = upk(acc[rp][0]), v1 = upk(acc[rp][1]);
            float2 v2 = upk(acc[rp][2]), v3 = upk(acc[rp][3]);
            if (r0 < n)
                *(float4*)(out + (size_t)r0 * H + c0) =
                    make_float4(fmaxf(v0.x + b4.x, 0.f), fmaxf(v1.x + b4.y, 0.f),
                                fmaxf(v2.x + b4.z, 0.f), fmaxf(v3.x + b4.w, 0.f));
            if (r1 < n)
                *(float4*)(out + (size_t)r1 * H + c0) =
                    make_float4(fmaxf(v0.y + b4.x, 0.f), fmaxf(v1.y + b4.y, 0.f),
                                fmaxf(v2.y + b4.z, 0.f), fmaxf(v3.y + b4.w, 0.f));
        }
        __syncwarp();
    }
}

// ---------------- u/v precompute, software-pipelined ----------------
__global__ void __launch_bounds__(TPB, 1)
uv_kernel(const float* __restrict__ x, const float* __restrict__ W1, float* __restrict__ u,
          float* __restrict__ v, int n) {
    extern __shared__ float sm[];
    float* Ws = sm;                           // full W1: 128KB
    float2* stage = (float2*)(sm + 256 * H);  // WARPS * NP_UV * 128 float2 = 36KB
    for (int i = threadIdx.x; i < 256 * H; i += TPB) Ws[i] = W1[i];
    __syncthreads();
    const int warp = threadIdx.x >> 5, lane = threadIdx.x & 31;
    const int c0 = lane * 4;
    float2* st = stage + warp * (NP_UV * 128);
    const int stride = gridDim.x * (WARPS * RPUV);
    int base = blockIdx.x * (WARPS * RPUV) + warp * RPUV;

    float4 px0[NP_UV], px1[NP_UV];
    const float4 z4 = make_float4(0.f, 0.f, 0.f, 0.f);
    if (base < n) {
#pragma unroll
        for (int rp = 0; rp < NP_UV; rp++) {
            int r0 = base + 2 * rp, r1 = r0 + 1;
            px0[rp] = z4; px1[rp] = z4;
            if (r0 < n) px0[rp] = *(const float4*)(x + (size_t)r0 * H + c0);
            if (r1 < n) px1[rp] = *(const float4*)(x + (size_t)r1 * H + c0);
        }
    }

    for (; base < n; base += stride) {
#pragma unroll
        for (int rp = 0; rp < NP_UV; rp++) {
            float2* b = st + rp * 128;
            *(float4*)(b + c0) = make_float4(px0[rp].x, px1[rp].x, px0[rp].y, px1[rp].y);
            *(float4*)(b + c0 + 2) = make_float4(px0[rp].z, px1[rp].z, px0[rp].w, px1[rp].w);
        }
        __syncwarp();

        int nb = base + stride;
        if (nb < n) {
#pragma unroll
            for (int rp = 0; rp < NP_UV; rp++) {
                int r0 = nb + 2 * rp, r1 = r0 + 1;
                px0[rp] = z4; px1[rp] = z4;
                if (r0 < n) px0[rp] = *(const float4*)(x + (size_t)r0 * H + c0);
                if (r1 < n) px1[rp] = *(const float4*)(x + (size_t)r1 * H + c0);
            }
        }

        u64 au[NP_UV][4], av[NP_UV][4];
#pragma unroll
        for (int rp = 0; rp < NP_UV; rp++)
#pragma unroll
            for (int c = 0; c < 4; c++) { au[rp][c] = 0ull; av[rp][c] = 0ull; }

#pragma unroll 2
        for (int k4 = 0; k4 < 32; k4++) {
            ulonglong2 ap0[NP_UV], ap1[NP_UV];
#pragma unroll
            for (int rp = 0; rp < NP_UV; rp++) {
                const float2* b = st + rp * 128 + 4 * k4;
                ap0[rp] = *(const ulonglong2*)(b);
                ap1[rp] = *(const ulonglong2*)(b + 2);
            }
#pragma unroll
            for (int j = 0; j < 4; j++) {
                int k = 4 * k4 + j;
                float4 wu = *(const float4*)(Ws + k * H + c0);
                float4 wv = *(const float4*)(Ws + (128 + k) * H + c0);
                u64 ua = pk2(wu.x, wu.x), ub = pk2(wu.y, wu.y);
                u64 uc = pk2(wu.z, wu.z), ud = pk2(wu.w, wu.w);
                u64 va = pk2(wv.x, wv.x), vb = pk2(wv.y, wv.y);
                u64 vc = pk2(wv.z, wv.z), vd = pk2(wv.w, wv.w);
#pragma unroll
                for (int rp = 0; rp < NP_UV; rp++) {
                    u64 a = (j == 0) ? ap0[rp].x : (j == 1) ? ap0[rp].y
                                                 : (j == 2) ? ap1[rp].x : ap1[rp].y;
                    fma2(au[rp][0], ua, a);
                    fma2(au[rp][1], ub, a);
                    fma2(au[rp][2], uc, a);
                    fma2(au[rp][3], ud, a);
                    fma2(av[rp][0], va, a);
                    fma2(av[rp][1], vb, a);
                    fma2(av[rp][2], vc, a);
                    fma2(av[rp][3], vd, a);
                }
            }
        }

#pragma unroll
        for (int rp = 0; rp < NP_UV; rp++) {
            int r0 = base + 2 * rp, r1 = r0 + 1;
            float2 a0 = upk(au[rp][0]), a1 = upk(au[rp][1]), a2 = upk(au[rp][2]),
                   a3 = upk(au[rp][3]);
            float2 b0 = upk(av[rp][0]), b1 = upk(av[rp][1]), b2 = upk(av[rp][2]),
                   b3 = upk(av[rp][3]);
            if (r0 < n) {
                *(float4*)(u + (size_t)r0 * H + c0) = make_float4(a0.x, a1.x, a2.x, a3.x);
                *(float4*)(v + (size_t)r0 * H + c0) = make_float4(b0.x, b1.x, b2.x, b3.x);
            }
            if (r1 < n) {
                *(float4*)(u + (size_t)r1 * H + c0) = make_float4(a0.y, a1.y, a2.y, a3.y);
                *(float4*)(v + (size_t)r1 * H + c0) = make_float4(b0.y, b1.y, b2.y, b3.y);
            }
        }
        __syncwarp();
    }
}

// ---------------- edge classifier: logits = relu(u[s]+v[d]+b1) @ W2 + b2 ----------------
__global__ void edge_kernel(const float* __restrict__ u, const float* __restrict__ v,
                            const int* __restrict__ qs, const int* __restrict__ qd,
                            const float* __restrict__ b1, const float* __restrict__ W2,
                            const float* __restrict__ b2, float* __restrict__ out, int nq) {
    __shared__ float W2s[H * 8];
    __shared__ float b1s[H];
    __shared__ float b2s[8];
    for (int i = threadIdx.x; i < H * 8; i += blockDim.x) W2s[i] = W2[i];
    for (int i = threadIdx.x; i < H; i += blockDim.x) b1s[i] = b1[i];
    if (threadIdx.x < 8) b2s[threadIdx.x] = b2[threadIdx.x];
    __syncthreads();

    int idx = blockIdx.x * blockDim.x + threadIdx.x;
    int stride = gridDim.x * blockDim.x;
    for (int e = idx; e < nq; e += stride) {
        size_t s = (size_t)qs[e];
        size_t d = (size_t)qd[e];
        const float4* ur = (const float4*)(u + s * H);
        const float4* vr = (const float4*)(v + d * H);
        float lg[8];
#pragma unroll
        for (int c = 0; c < 8; c++) lg[c] = b2s[c];
#pragma unroll 8
        for (int k4 = 0; k4 < 32; k4++) {
            float4 a = __ldg(ur + k4);
            float4 b = __ldg(vr + k4);
            float h0 = fmaxf(a.x + b.x + b1s[k4 * 4 + 0], 0.f);
            float h1 = fmaxf(a.y + b.y + b1s[k4 * 4 + 1], 0.f);
            float h2 = fmaxf(a.z + b.z + b1s[k4 * 4 + 2], 0.f);
            float h3 = fmaxf(a.w + b.w + b1s[k4 * 4 + 3], 0.f);
#pragma unroll
            for (int c = 0; c < 8; c++) {
                lg[c] += h0 * W2s[(k4 * 4 + 0) * 8 + c];
                lg[c] += h1 * W2s[(k4 * 4 + 1) * 8 + c];
                lg[c] += h2 * W2s[(k4 * 4 + 2) * 8 + c];
                lg[c] += h3 * W2s[(k4 * 4 + 3) * 8 + c];
            }
        }
        float4* op = (float4*)(out + (size_t)e * 8);
        op[0] = make_float4(lg[0], lg[1], lg[2], lg[3]);
        op[1] = make_float4(lg[4], lg[5], lg[6], lg[7]);
    }
}

// ---------------- host ----------------
#define SMEM_LAYER (256 * H * 4 + WARPS * NP_L * 256 * 8)  // 128KB + 72KB = 200KB
#define SMEM_UV (256 * H * 4 + WARPS * NP_UV * 128 * 8)    // 128KB + 36KB = 164KB

extern "C" void kernel_launch(void* const* d_in, const int* in_sizes, int n_in, void* d_out,
                              int out_size) {
    const float* node_emb = (const float*)d_in[0];
    const float* Wl0 = (const float*)d_in[1];
    const float* bl0 = (const float*)d_in[2];
    const float* Wr0 = (const float*)d_in[3];
    const float* Wl1 = (const float*)d_in[4];
    const float* bl1 = (const float*)d_in[5];
    const float* Wr1 = (const float*)d_in[6];
    const float* mW1 = (const float*)d_in[7];
    const float* mb1 = (const float*)d_in[8];
    const float* mW2 = (const float*)d_in[9];
    const float* mb2 = (const float*)d_in[10];
    const int* eidx = (const int*)d_in[11];  // int32 (JAX x64 disabled)
    const int* eq = (const int*)d_in[12];    // int32

    const int n = in_sizes[0] / H;    // 100000
    const int nE = in_sizes[11] / 2;  // 1600000
    const int nq = in_sizes[12] / 2;  // 500000

    float *mean, *x1, *x2, *u, *v;
    int *cnt, *off, *cur, *bsum, *csr;
    cudaGetSymbolAddress((void**)&mean, g_mean);
    cudaGetSymbolAddress((void**)&x1, g_x1);
    cudaGetSymbolAddress((void**)&x2, g_x2);
    cudaGetSymbolAddress((void**)&u, g_u);
    cudaGetSymbolAddress((void**)&v, g_v);
    cudaGetSymbolAddress((void**)&cnt, g_cnt);
    cudaGetSymbolAddress((void**)&off, g_off);
    cudaGetSymbolAddress((void**)&cur, g_cur);
    cudaGetSymbolAddress((void**)&bsum, g_bsum);
    cudaGetSymbolAddress((void**)&csr, g_csr);

    int sms = 148;
    cudaDeviceGetAttribute(&sms, cudaDevAttrMultiProcessorCount, 0);
    cudaFuncSetAttribute(layer_kernel, cudaFuncAttributeMaxDynamicSharedMemorySize, SMEM_LAYER);
    cudaFuncSetAttribute(uv_kernel, cudaFuncAttributeMaxDynamicSharedMemorySize, SMEM_UV);

    const int* esrc = eidx;
    const int* edst = eidx + nE;
    const int nscan = (n + 1023) / 1024;  // 98 blocks

    // ---- CSR build (once; shared by both layers) ----
    zeroi_kernel<<<(n + 255) / 256, 256>>>(cnt, n);
    hist_kernel<<<sms * 8, 256>>>(edst, cnt, nE);
    scan1_kernel<<<nscan, 1024>>>(cnt, off, bsum, n);
    scan2_kernel<<<1, 128>>>(bsum, nscan);
    scan3_kernel<<<(n + 255) / 256, 256>>>(off, bsum, cur, n, nE);
    fill_kernel<<<sms * 8, 256>>>(esrc, edst, cur, csr, nE);

    const int gather_blocks = (n * 32 + 255) / 256;

    // ---- layer 0 ----
    gather_kernel<<<gather_blocks, 256>>>(node_emb, csr, off, mean, n);
    layer_kernel<<<sms, TPB, SMEM_LAYER>>>(node_emb, mean, Wl0, Wr0, bl0, x1, n);

    // ---- layer 1 ----
    gather_kernel<<<gather_blocks, 256>>>(x1, csr, off, mean, n);
    layer_kernel<<<sms, TPB, SMEM_LAYER>>>(x1, mean, Wl1, Wr1, bl1, x2, n);

    // ---- edge classifier ----
    uv_kernel<<<sms, TPB, SMEM_UV>>>(x2, mW1, u, v, n);
    edge_kernel<<<(nq + 255) / 256, 256>>>(u, v, eq, eq + nq, mb1, mW2, mb2, (float*)d_out, nq);
}

// round 16
// speedup vs baseline: 1.0393x; 1.0393x over previous
#include <cuda_runtime.h>

#define H 128
#define MAXN 100000
#define MAXE 1600000
#define TPB 384
#define WARPS 12
#define NP_L 4
#define RPL 8
#define NP_UV 4
#define RPUV 8

// ---------------- scratch (device globals; no allocations anywhere) ----------------
__device__ __align__(128) float g_mean[MAXN * H];
__device__ __align__(128) float g_x1[MAXN * H];
__device__ __align__(128) float g_x2[MAXN * H];
__device__ __align__(128) float g_u[MAXN * H];
__device__ __align__(128) float g_v[MAXN * H];
__device__ __align__(128) int g_cnt[MAXN];
__device__ __align__(128) int g_off[MAXN + 1];
__device__ __align__(128) int g_cur[MAXN];
__device__ __align__(128) int g_bsum[128];
__device__ __align__(128) int g_csr[MAXE];
__device__ __align__(128) int g_ctr[4];  // dynamic tile counters (layer0, layer1, uv)

typedef unsigned long long u64;

static __device__ __forceinline__ u64 pk2(float a, float b) {
    u64 r;
    asm("mov.b64 %0, {%1,%2};" : "=l"(r) : "f"(a), "f"(b));
    return r;
}
static __device__ __forceinline__ void fma2(u64& d, u64 a, u64 b) {
    asm("fma.rn.f32x2 %0, %1, %2, %0;" : "+l"(d) : "l"(a), "l"(b));
}
static __device__ __forceinline__ float2 upk(u64 a) {
    float2 r;
    asm("mov.b64 {%0,%1}, %2;" : "=f"(r.x), "=f"(r.y) : "l"(a));
    return r;
}

// warp-uniform dynamic tile fetch
static __device__ __forceinline__ int next_tile(int* ctr, int lane) {
    int t;
    if (lane == 0) t = atomicAdd(ctr, 1);
    return __shfl_sync(0xffffffffu, t, 0);
}

// ---------------- CSR construction ----------------
__global__ void zeroi_kernel(int* p, int n) {
    int i = blockIdx.x * blockDim.x + threadIdx.x;
    if (i < n) p[i] = 0;
}
__global__ void hist_kernel(const int* __restrict__ dst, int* __restrict__ cnt, int nE) {
    int i = blockIdx.x * blockDim.x + threadIdx.x;
    int stride = gridDim.x * blockDim.x;
    for (int e = i; e < nE; e += stride) atomicAdd(cnt + dst[e], 1);
}
__global__ void scan1_kernel(const int* __restrict__ cnt, int* __restrict__ off,
                             int* __restrict__ bsum, int n) {
    __shared__ int sm[1024];
    int i = blockIdx.x * 1024 + threadIdx.x;
    int v = (i < n) ? cnt[i] : 0;
    sm[threadIdx.x] = v;
    __syncthreads();
    for (int d = 1; d < 1024; d <<= 1) {
        int t = (threadIdx.x >= d) ? sm[threadIdx.x - d] : 0;
        __syncthreads();
        sm[threadIdx.x] += t;
        __syncthreads();
    }
    if (i < n) off[i] = sm[threadIdx.x] - v;  // exclusive
    if (threadIdx.x == 1023) bsum[blockIdx.x] = sm[1023];
}
__global__ void scan2_kernel(int* bsum, int nb) {
    __shared__ int sm[128];
    int v = (threadIdx.x < nb) ? bsum[threadIdx.x] : 0;
    sm[threadIdx.x] = v;
    __syncthreads();
    for (int d = 1; d < 128; d <<= 1) {
        int t = (threadIdx.x >= d) ? sm[threadIdx.x - d] : 0;
        __syncthreads();
        sm[threadIdx.x] += t;
        __syncthreads();
    }
    if (threadIdx.x < nb) bsum[threadIdx.x] = sm[threadIdx.x] - v;  // exclusive
}
__global__ void scan3_kernel(int* __restrict__ off, const int* __restrict__ bsum,
                             int* __restrict__ cur, int n, int nE) {
    int i = blockIdx.x * blockDim.x + threadIdx.x;
    if (i < n) {
        int o = off[i] + bsum[i >> 10];
        off[i] = o;
        cur[i] = o;
    }
    if (i == 0) off[n] = nE;
}
__global__ void fill_kernel(const int* __restrict__ src, const int* __restrict__ dst,
                            int* __restrict__ cur, int* __restrict__ csr, int nE) {
    int i = blockIdx.x * blockDim.x + threadIdx.x;
    int stride = gridDim.x * blockDim.x;
    for (int e = i; e < nE; e += stride) {
        int pos = atomicAdd(cur + dst[e], 1);
        csr[pos] = src[e];
    }
}

// ---------------- gather-aggregate: mean[node] = sum_{src in N(node)} x[src] / max(deg,1) ----------------
__global__ void gather_kernel(const float* __restrict__ x, const int* __restrict__ csr,
                              const int* __restrict__ off, float* __restrict__ mean, int n) {
    int w = (blockIdx.x * blockDim.x + threadIdx.x) >> 5;
    if (w >= n) return;
    int lane = threadIdx.x & 31;
    int c0 = lane * 4;
    int e0 = off[w], e1 = off[w + 1];
    float4 a0 = make_float4(0.f, 0.f, 0.f, 0.f), a1 = a0, a2 = a0, a3 = a0;
    int e = e0;
    for (; e + 4 <= e1; e += 4) {
        int i0 = csr[e], i1 = csr[e + 1], i2 = csr[e + 2], i3 = csr[e + 3];
        float4 v0 = *(const float4*)(x + (size_t)i0 * H + c0);
        float4 v1 = *(const float4*)(x + (size_t)i1 * H + c0);
        float4 v2 = *(const float4*)(x + (size_t)i2 * H + c0);
        float4 v3 = *(const float4*)(x + (size_t)i3 * H + c0);
        a0.x += v0.x; a0.y += v0.y; a0.z += v0.z; a0.w += v0.w;
        a1.x += v1.x; a1.y += v1.y; a1.z += v1.z; a1.w += v1.w;
        a2.x += v2.x; a2.y += v2.y; a2.z += v2.z; a2.w += v2.w;
        a3.x += v3.x; a3.y += v3.y; a3.z += v3.z; a3.w += v3.w;
    }
    for (; e < e1; e++) {
        int i0 = csr[e];
        float4 v0 = *(const float4*)(x + (size_t)i0 * H + c0);
        a0.x += v0.x; a0.y += v0.y; a0.z += v0.z; a0.w += v0.w;
    }
    float rd = 1.0f / fmaxf((float)(e1 - e0), 1.0f);
    float4 acc;
    acc.x = (a0.x + a1.x + a2.x + a3.x) * rd;
    acc.y = (a0.y + a1.y + a2.y + a3.y) * rd;
    acc.z = (a0.z + a1.z + a2.z + a3.z) * rd;
    acc.w = (a0.w + a1.w + a2.w + a3.w) * rd;
    *(float4*)(mean + (size_t)w * H + c0) = acc;
}

// ---------------- fused SAGE layer (R11 body + dynamic warp-tiles) ----------------
// out = relu(mean@Wl + x@Wr + b). Row-pair f32x2 compute; warps pull 8-row tiles
// from a global counter to eliminate the 7.04->8 static-stride tail.
__global__ void __launch_bounds__(TPB, 1)
layer_kernel(const float* __restrict__ x, const float* __restrict__ mean,
             const float* __restrict__ Wl, const float* __restrict__ Wr,
             const float* __restrict__ bias, float* __restrict__ out, int* ctr, int n) {
    extern __shared__ float sm[];
    float* Ws = sm;                           // 256*128 floats = 128KB (Wl rows then Wr rows)
    float2* stage = (float2*)(sm + 256 * H);  // WARPS * NP_L * 256 float2 = 96KB
    for (int i = threadIdx.x; i < H * H; i += TPB) {
        Ws[i] = Wl[i];
        Ws[H * H + i] = Wr[i];
    }
    __syncthreads();
    const int warp = threadIdx.x >> 5, lane = threadIdx.x & 31;
    const int c0 = lane * 4;
    float2* st = stage + warp * (NP_L * 256);
    const float4 b4 = *(const float4*)(bias + c0);
    const int ntiles = (n + RPL - 1) / RPL;

    for (;;) {
        int t = next_tile(ctr, lane);
        if (t >= ntiles) break;
        int base = t * RPL;
#pragma unroll
        for (int rp = 0; rp < NP_L; rp++) {
            int r0 = base + 2 * rp, r1 = r0 + 1;
            float4 m0 = make_float4(0.f, 0.f, 0.f, 0.f), m1 = m0, x0 = m0, x1 = m0;
            if (r0 < n) {
                m0 = *(const float4*)(mean + (size_t)r0 * H + c0);
                x0 = *(const float4*)(x + (size_t)r0 * H + c0);
            }
            if (r1 < n) {
                m1 = *(const float4*)(mean + (size_t)r1 * H + c0);
                x1 = *(const float4*)(x + (size_t)r1 * H + c0);
            }
            float2* b = st + rp * 256;
            *(float4*)(b + c0) = make_float4(m0.x, m1.x, m0.y, m1.y);
            *(float4*)(b + c0 + 2) = make_float4(m0.z, m1.z, m0.w, m1.w);
            *(float4*)(b + 128 + c0) = make_float4(x0.x, x1.x, x0.y, x1.y);
            *(float4*)(b + 128 + c0 + 2) = make_float4(x0.z, x1.z, x0.w, x1.w);
        }
        __syncwarp();

        u64 acc[NP_L][4];
#pragma unroll
        for (int rp = 0; rp < NP_L; rp++)
#pragma unroll
            for (int c = 0; c < 4; c++) acc[rp][c] = 0ull;

#pragma unroll 2
        for (int k4 = 0; k4 < 64; k4++) {
            ulonglong2 ap0[NP_L], ap1[NP_L];
#pragma unroll
            for (int rp = 0; rp < NP_L; rp++) {
                const float2* b = st + rp * 256 + 4 * k4;
                ap0[rp] = *(const ulonglong2*)(b);
                ap1[rp] = *(const ulonglong2*)(b + 2);
            }
#pragma unroll
            for (int j = 0; j < 4; j++) {
                float4 w = *(const float4*)(Ws + (4 * k4 + j) * H + c0);
                u64 wa = pk2(w.x, w.x), wb = pk2(w.y, w.y);
                u64 wc = pk2(w.z, w.z), wd = pk2(w.w, w.w);
#pragma unroll
                for (int rp = 0; rp < NP_L; rp++) {
                    u64 a = (j == 0) ? ap0[rp].x : (j == 1) ? ap0[rp].y
                                                 : (j == 2) ? ap1[rp].x : ap1[rp].y;
                    fma2(acc[rp][0], wa, a);
                    fma2(acc[rp][1], wb, a);
                    fma2(acc[rp][2], wc, a);
                    fma2(acc[rp][3], wd, a);
                }
            }
        }

#pragma unroll
        for (int rp = 0; rp < NP_L; rp++) {
            int r0 = base + 2 * rp, r1 = r0 + 1;
            float2 v0 = upk(acc[rp][0]), v1 = upk(acc[rp][1]);
            float2 v2 = upk(acc[rp][2]), v3 = upk(acc[rp][3]);
            if (r0 < n)
                *(float4*)(out + (size_t)r0 * H + c0) =
                    make_float4(fmaxf(v0.x + b4.x, 0.f), fmaxf(v1.x + b4.y, 0.f),
                                fmaxf(v2.x + b4.z, 0.f), fmaxf(v3.x + b4.w, 0.f));
            if (r1 < n)
                *(float4*)(out + (size_t)r1 * H + c0) =
                    make_float4(fmaxf(v0.y + b4.x, 0.f), fmaxf(v1.y + b4.y, 0.f),
                                fmaxf(v2.y + b4.z, 0.f), fmaxf(v3.y + b4.w, 0.f));
        }
        __syncwarp();
    }
}

// ---------------- u/v precompute (R11 body + dynamic warp-tiles) ----------------
__global__ void __launch_bounds__(TPB, 1)
uv_kernel(const float* __restrict__ x, const float* __restrict__ W1, float* __restrict__ u,
          float* __restrict__ v, int* ctr, int n) {
    extern __shared__ float sm[];
    float* Ws = sm;                           // full W1: 256*128 floats = 128KB
    float2* stage = (float2*)(sm + 256 * H);  // WARPS * NP_UV * 128 float2 = 48KB
    for (int i = threadIdx.x; i < 256 * H; i += TPB) Ws[i] = W1[i];
    __syncthreads();
    const int warp = threadIdx.x >> 5, lane = threadIdx.x & 31;
    const int c0 = lane * 4;
    float2* st = stage + warp * (NP_UV * 128);
    const int ntiles = (n + RPUV - 1) / RPUV;

    for (;;) {
        int t = next_tile(ctr, lane);
        if (t >= ntiles) break;
        int base = t * RPUV;
#pragma unroll
        for (int rp = 0; rp < NP_UV; rp++) {
            int r0 = base + 2 * rp, r1 = r0 + 1;
            float4 x0 = make_float4(0.f, 0.f, 0.f, 0.f), x1 = x0;
            if (r0 < n) x0 = *(const float4*)(x + (size_t)r0 * H + c0);
            if (r1 < n) x1 = *(const float4*)(x + (size_t)r1 * H + c0);
            float2* b = st + rp * 128;
            *(float4*)(b + c0) = make_float4(x0.x, x1.x, x0.y, x1.y);
            *(float4*)(b + c0 + 2) = make_float4(x0.z, x1.z, x0.w, x1.w);
        }
        __syncwarp();

        u64 au[NP_UV][4], av[NP_UV][4];
#pragma unroll
        for (int rp = 0; rp < NP_UV; rp++)
#pragma unroll
            for (int c = 0; c < 4; c++) { au[rp][c] = 0ull; av[rp][c] = 0ull; }

#pragma unroll 2
        for (int k4 = 0; k4 < 32; k4++) {
            ulonglong2 ap0[NP_UV], ap1[NP_UV];
#pragma unroll
            for (int rp = 0; rp < NP_UV; rp++) {
                const float2* b = st + rp * 128 + 4 * k4;
                ap0[rp] = *(const ulonglong2*)(b);
                ap1[rp] = *(const ulonglong2*)(b + 2);
            }
#pragma unroll
            for (int j = 0; j < 4; j++) {
                int k = 4 * k4 + j;
                float4 wu = *(const float4*)(Ws + k * H + c0);
                float4 wv = *(const float4*)(Ws + (128 + k) * H + c0);
                u64 ua = pk2(wu.x, wu.x), ub = pk2(wu.y, wu.y);
                u64 uc = pk2(wu.z, wu.z), ud = pk2(wu.w, wu.w);
                u64 va = pk2(wv.x, wv.x), vb = pk2(wv.y, wv.y);
                u64 vc = pk2(wv.z, wv.z), vd = pk2(wv.w, wv.w);
#pragma unroll
                for (int rp = 0; rp < NP_UV; rp++) {
                    u64 a = (j == 0) ? ap0[rp].x : (j == 1) ? ap0[rp].y
                                                 : (j == 2) ? ap1[rp].x : ap1[rp].y;
                    fma2(au[rp][0], ua, a);
                    fma2(au[rp][1], ub, a);
                    fma2(au[rp][2], uc, a);
                    fma2(au[rp][3], ud, a);
                    fma2(av[rp][0], va, a);
                    fma2(av[rp][1], vb, a);
                    fma2(av[rp][2], vc, a);
                    fma2(av[rp][3], vd, a);
                }
            }
        }

#pragma unroll
        for (int rp = 0; rp < NP_UV; rp++) {
            int r0 = base + 2 * rp, r1 = r0 + 1;
            float2 a0 = upk(au[rp][0]), a1 = upk(au[rp][1]), a2 = upk(au[rp][2]),
                   a3 = upk(au[rp][3]);
            float2 b0 = upk(av[rp][0]), b1 = upk(av[rp][1]), b2 = upk(av[rp][2]),
                   b3 = upk(av[rp][3]);
            if (r0 < n) {
                *(float4*)(u + (size_t)r0 * H + c0) = make_float4(a0.x, a1.x, a2.x, a3.x);
                *(float4*)(v + (size_t)r0 * H + c0) = make_float4(b0.x, b1.x, b2.x, b3.x);
            }
            if (r1 < n) {
                *(float4*)(u + (size_t)r1 * H + c0) = make_float4(a0.y, a1.y, a2.y, a3.y);
                *(float4*)(v + (size_t)r1 * H + c0) = make_float4(b0.y, b1.y, b2.y, b3.y);
            }
        }
        __syncwarp();
    }
}

// ---------------- edge classifier: logits = relu(u[s]+v[d]+b1) @ W2 + b2 ----------------
__global__ void edge_kernel(const float* __restrict__ u, const float* __restrict__ v,
                            const int* __restrict__ qs, const int* __restrict__ qd,
                            const float* __restrict__ b1, const float* __restrict__ W2,
                            const float* __restrict__ b2, float* __restrict__ out, int nq) {
    __shared__ float W2s[H * 8];
    __shared__ float b1s[H];
    __shared__ float b2s[8];
    for (int i = threadIdx.x; i < H * 8; i += blockDim.x) W2s[i] = W2[i];
    for (int i = threadIdx.x; i < H; i += blockDim.x) b1s[i] = b1[i];
    if (threadIdx.x < 8) b2s[threadIdx.x] = b2[threadIdx.x];
    __syncthreads();

    int idx = blockIdx.x * blockDim.x + threadIdx.x;
    int stride = gridDim.x * blockDim.x;
    for (int e = idx; e < nq; e += stride) {
        size_t s = (size_t)qs[e];
        size_t d = (size_t)qd[e];
        const float4* ur = (const float4*)(u + s * H);
        const float4* vr = (const float4*)(v + d * H);
        float lg[8];
#pragma unroll
        for (int c = 0; c < 8; c++) lg[c] = b2s[c];
#pragma unroll 8
        for (int k4 = 0; k4 < 32; k4++) {
            float4 a = __ldg(ur + k4);
            float4 b = __ldg(vr + k4);
            float h0 = fmaxf(a.x + b.x + b1s[k4 * 4 + 0], 0.f);
            float h1 = fmaxf(a.y + b.y + b1s[k4 * 4 + 1], 0.f);
            float h2 = fmaxf(a.z + b.z + b1s[k4 * 4 + 2], 0.f);
            float h3 = fmaxf(a.w + b.w + b1s[k4 * 4 + 3], 0.f);
#pragma unroll
            for (int c = 0; c < 8; c++) {
                lg[c] += h0 * W2s[(k4 * 4 + 0) * 8 + c];
                lg[c] += h1 * W2s[(k4 * 4 + 1) * 8 + c];
                lg[c] += h2 * W2s[(k4 * 4 + 2) * 8 + c];
                lg[c] += h3 * W2s[(k4 * 4 + 3) * 8 + c];
            }
        }
        float4* op = (float4*)(out + (size_t)e * 8);
        op[0] = make_float4(lg[0], lg[1], lg[2], lg[3]);
        op[1] = make_float4(lg[4], lg[5], lg[6], lg[7]);
    }
}

// ---------------- host ----------------
#define SMEM_LAYER (256 * H * 4 + WARPS * NP_L * 256 * 8)  // 128KB + 96KB = 224KB
#define SMEM_UV (256 * H * 4 + WARPS * NP_UV * 128 * 8)    // 128KB + 48KB = 176KB

extern "C" void kernel_launch(void* const* d_in, const int* in_sizes, int n_in, void* d_out,
                              int out_size) {
    const float* node_emb = (const float*)d_in[0];
    const float* Wl0 = (const float*)d_in[1];
    const float* bl0 = (const float*)d_in[2];
    const float* Wr0 = (const float*)d_in[3];
    const float* Wl1 = (const float*)d_in[4];
    const float* bl1 = (const float*)d_in[5];
    const float* Wr1 = (const float*)d_in[6];
    const float* mW1 = (const float*)d_in[7];
    const float* mb1 = (const float*)d_in[8];
    const float* mW2 = (const float*)d_in[9];
    const float* mb2 = (const float*)d_in[10];
    const int* eidx = (const int*)d_in[11];  // int32 (JAX x64 disabled)
    const int* eq = (const int*)d_in[12];    // int32

    const int n = in_sizes[0] / H;    // 100000
    const int nE = in_sizes[11] / 2;  // 1600000
    const int nq = in_sizes[12] / 2;  // 500000

    float *mean, *x1, *x2, *u, *v;
    int *cnt, *off, *cur, *bsum, *csr, *ctr;
    cudaGetSymbolAddress((void**)&mean, g_mean);
    cudaGetSymbolAddress((void**)&x1, g_x1);
    cudaGetSymbolAddress((void**)&x2, g_x2);
    cudaGetSymbolAddress((void**)&u, g_u);
    cudaGetSymbolAddress((void**)&v, g_v);
    cudaGetSymbolAddress((void**)&cnt, g_cnt);
    cudaGetSymbolAddress((void**)&off, g_off);
    cudaGetSymbolAddress((void**)&cur, g_cur);
    cudaGetSymbolAddress((void**)&bsum, g_bsum);
    cudaGetSymbolAddress((void**)&csr, g_csr);
    cudaGetSymbolAddress((void**)&ctr, g_ctr);

    int sms = 148;
    cudaDeviceGetAttribute(&sms, cudaDevAttrMultiProcessorCount, 0);
    cudaFuncSetAttribute(layer_kernel, cudaFuncAttributeMaxDynamicSharedMemorySize, SMEM_LAYER);
    cudaFuncSetAttribute(uv_kernel, cudaFuncAttributeMaxDynamicSharedMemorySize, SMEM_UV);

    const int* esrc = eidx;
    const int* edst = eidx + nE;
    const int nscan = (n + 1023) / 1024;  // 98 blocks

    // ---- CSR build (once; shared by both layers) + tile-counter reset ----
    zeroi_kernel<<<(n + 255) / 256, 256>>>(cnt, n);
    zeroi_kernel<<<1, 32>>>(ctr, 4);
    hist_kernel<<<sms * 8, 256>>>(edst, cnt, nE);
    scan1_kernel<<<nscan, 1024>>>(cnt, off, bsum, n);
    scan2_kernel<<<1, 128>>>(bsum, nscan);
    scan3_kernel<<<(n + 255) / 256, 256>>>(off, bsum, cur, n, nE);
    fill_kernel<<<sms * 8, 256>>>(esrc, edst, cur, csr, nE);

    const int gather_blocks = (n * 32 + 255) / 256;

    // ---- layer 0 ----
    gather_kernel<<<gather_blocks, 256>>>(node_emb, csr, off, mean, n);
    layer_kernel<<<sms, TPB, SMEM_LAYER>>>(node_emb, mean, Wl0, Wr0, bl0, x1, ctr + 0, n);

    // ---- layer 1 ----
    gather_kernel<<<gather_blocks, 256>>>(x1, csr, off, mean, n);
    layer_kernel<<<sms, TPB, SMEM_LAYER>>>(x1, mean, Wl1, Wr1, bl1, x2, ctr + 1, n);

    // ---- edge classifier ----
    uv_kernel<<<sms, TPB, SMEM_UV>>>(x2, mW1, u, v, ctr + 2, n);
    edge_kernel<<<(nq + 255) / 256, 256>>>(u, v, eq, eq + nq, mb1, mW2, mb2, (float*)d_out, nq);
}

// round 17
// speedup vs baseline: 1.0439x; 1.0045x over previous
#include <cuda_runtime.h>

#define H 128
#define MAXN 100000
#define MAXE 1600000
#define TPB 384
#define WARPS 12
#define NP_L 6
#define RPL 12
#define NP_UV 4
#define RPUV 8

// ---------------- scratch (device globals; no allocations anywhere) ----------------
__device__ __align__(128) float g_mean[MAXN * H];
__device__ __align__(128) float g_x1[MAXN * H];
__device__ __align__(128) float g_x2[MAXN * H];
__device__ __align__(128) float g_u[MAXN * H];
__device__ __align__(128) float g_v[MAXN * H];
__device__ __align__(128) int g_cnt[MAXN];
__device__ __align__(128) int g_off[MAXN + 1];
__device__ __align__(128) int g_cur[MAXN];
__device__ __align__(128) int g_bsum[128];
__device__ __align__(128) int g_csr[MAXE];
__device__ __align__(128) int g_ctr[4];  // dynamic tile counters (layer0, layer1, uv)

typedef unsigned long long u64;

static __device__ __forceinline__ u64 pk2(float a, float b) {
    u64 r;
    asm("mov.b64 %0, {%1,%2};" : "=l"(r) : "f"(a), "f"(b));
    return r;
}
static __device__ __forceinline__ void fma2(u64& d, u64 a, u64 b) {
    asm("fma.rn.f32x2 %0, %1, %2, %0;" : "+l"(d) : "l"(a), "l"(b));
}
static __device__ __forceinline__ float2 upk(u64 a) {
    float2 r;
    asm("mov.b64 {%0,%1}, %2;" : "=f"(r.x), "=f"(r.y) : "l"(a));
    return r;
}

// warp-uniform dynamic tile fetch
static __device__ __forceinline__ int next_tile(int* ctr, int lane) {
    int t;
    if (lane == 0) t = atomicAdd(ctr, 1);
    return __shfl_sync(0xffffffffu, t, 0);
}

// ---------------- CSR construction ----------------
__global__ void zeroi_kernel(int* p, int n) {
    int i = blockIdx.x * blockDim.x + threadIdx.x;
    if (i < n) p[i] = 0;
}
__global__ void hist_kernel(const int* __restrict__ dst, int* __restrict__ cnt, int nE) {
    int i = blockIdx.x * blockDim.x + threadIdx.x;
    int stride = gridDim.x * blockDim.x;
    for (int e = i; e < nE; e += stride) atomicAdd(cnt + dst[e], 1);
}
__global__ void scan1_kernel(const int* __restrict__ cnt, int* __restrict__ off,
                             int* __restrict__ bsum, int n) {
    __shared__ int sm[1024];
    int i = blockIdx.x * 1024 + threadIdx.x;
    int v = (i < n) ? cnt[i] : 0;
    sm[threadIdx.x] = v;
    __syncthreads();
    for (int d = 1; d < 1024; d <<= 1) {
        int t = (threadIdx.x >= d) ? sm[threadIdx.x - d] : 0;
        __syncthreads();
        sm[threadIdx.x] += t;
        __syncthreads();
    }
    if (i < n) off[i] = sm[threadIdx.x] - v;  // exclusive
    if (threadIdx.x == 1023) bsum[blockIdx.x] = sm[1023];
}
__global__ void scan2_kernel(int* bsum, int nb) {
    __shared__ int sm[128];
    int v = (threadIdx.x < nb) ? bsum[threadIdx.x] : 0;
    sm[threadIdx.x] = v;
    __syncthreads();
    for (int d = 1; d < 128; d <<= 1) {
        int t = (threadIdx.x >= d) ? sm[threadIdx.x - d] : 0;
        __syncthreads();
        sm[threadIdx.x] += t;
        __syncthreads();
    }
    if (threadIdx.x < nb) bsum[threadIdx.x] = sm[threadIdx.x] - v;  // exclusive
}
__global__ void scan3_kernel(int* __restrict__ off, const int* __restrict__ bsum,
                             int* __restrict__ cur, int n, int nE) {
    int i = blockIdx.x * blockDim.x + threadIdx.x;
    if (i < n) {
        int o = off[i] + bsum[i >> 10];
        off[i] = o;
        cur[i] = o;
    }
    if (i == 0) off[n] = nE;
}
__global__ void fill_kernel(const int* __restrict__ src, const int* __restrict__ dst,
                            int* __restrict__ cur, int* __restrict__ csr, int nE) {
    int i = blockIdx.x * blockDim.x + threadIdx.x;
    int stride = gridDim.x * blockDim.x;
    for (int e = i; e < nE; e += stride) {
        int pos = atomicAdd(cur + dst[e], 1);
        csr[pos] = src[e];
    }
}

// ---------------- gather-aggregate: mean[node] = sum_{src in N(node)} x[src] / max(deg,1) ----------------
__global__ void gather_kernel(const float* __restrict__ x, const int* __restrict__ csr,
                              const int* __restrict__ off, float* __restrict__ mean, int n) {
    int w = (blockIdx.x * blockDim.x + threadIdx.x) >> 5;
    if (w >= n) return;
    int lane = threadIdx.x & 31;
    int c0 = lane * 4;
    int e0 = off[w], e1 = off[w + 1];
    float4 a0 = make_float4(0.f, 0.f, 0.f, 0.f), a1 = a0, a2 = a0, a3 = a0;
    int e = e0;
    for (; e + 4 <= e1; e += 4) {
        int i0 = csr[e], i1 = csr[e + 1], i2 = csr[e + 2], i3 = csr[e + 3];
        float4 v0 = *(const float4*)(x + (size_t)i0 * H + c0);
        float4 v1 = *(const float4*)(x + (size_t)i1 * H + c0);
        float4 v2 = *(const float4*)(x + (size_t)i2 * H + c0);
        float4 v3 = *(const float4*)(x + (size_t)i3 * H + c0);
        a0.x += v0.x; a0.y += v0.y; a0.z += v0.z; a0.w += v0.w;
        a1.x += v1.x; a1.y += v1.y; a1.z += v1.z; a1.w += v1.w;
        a2.x += v2.x; a2.y += v2.y; a2.z += v2.z; a2.w += v2.w;
        a3.x += v3.x; a3.y += v3.y; a3.z += v3.z; a3.w += v3.w;
    }
    for (; e < e1; e++) {
        int i0 = csr[e];
        float4 v0 = *(const float4*)(x + (size_t)i0 * H + c0);
        a0.x += v0.x; a0.y += v0.y; a0.z += v0.z; a0.w += v0.w;
    }
    float rd = 1.0f / fmaxf((float)(e1 - e0), 1.0f);
    float4 acc;
    acc.x = (a0.x + a1.x + a2.x + a3.x) * rd;
    acc.y = (a0.y + a1.y + a2.y + a3.y) * rd;
    acc.z = (a0.z + a1.z + a2.z + a3.z) * rd;
    acc.w = (a0.w + a1.w + a2.w + a3.w) * rd;
    *(float4*)(mean + (size_t)w * H + c0) = acc;
}

// ---------------- fused SAGE layer: two-phase staging, 12 rows/warp ----------------
// out = relu(mean@Wl + x@Wr + b). Phase A stages the mean tile and accumulates
// k=0..127 (Wl); the SAME stage buffer is then overwritten with the x tile for
// k=128..255 (Wr). Halving the stage footprint permits NP_L=6 (12 rows/warp),
// amortizing weight LDS + pk2 movs over 1.5x more FFMA2s.
__global__ void __launch_bounds__(TPB, 1)
layer_kernel(const float* __restrict__ x, const float* __restrict__ mean,
             const float* __restrict__ Wl, const float* __restrict__ Wr,
             const float* __restrict__ bias, float* __restrict__ out, int* ctr, int n) {
    extern __shared__ float sm[];
    float* Ws = sm;                           // 256*128 floats = 128KB (Wl rows then Wr rows)
    float2* stage = (float2*)(sm + 256 * H);  // WARPS * NP_L * 128 float2 = 72KB
    for (int i = threadIdx.x; i < H * H; i += TPB) {
        Ws[i] = Wl[i];
        Ws[H * H + i] = Wr[i];
    }
    __syncthreads();
    const int warp = threadIdx.x >> 5, lane = threadIdx.x & 31;
    const int c0 = lane * 4;
    float2* st = stage + warp * (NP_L * 128);
    const float4 b4 = *(const float4*)(bias + c0);
    const int ntiles = (n + RPL - 1) / RPL;

    for (;;) {
        int t = next_tile(ctr, lane);
        if (t >= ntiles) break;
        int base = t * RPL;

        u64 acc[NP_L][4];
#pragma unroll
        for (int rp = 0; rp < NP_L; rp++)
#pragma unroll
            for (int c = 0; c < 4; c++) acc[rp][c] = 0ull;

        // ======== phase A: mean @ Wl (k = 0..127) ========
#pragma unroll
        for (int rp = 0; rp < NP_L; rp++) {
            int r0 = base + 2 * rp, r1 = r0 + 1;
            float4 m0 = make_float4(0.f, 0.f, 0.f, 0.f), m1 = m0;
            if (r0 < n) m0 = *(const float4*)(mean + (size_t)r0 * H + c0);
            if (r1 < n) m1 = *(const float4*)(mean + (size_t)r1 * H + c0);
            float2* b = st + rp * 128;
            *(float4*)(b + c0) = make_float4(m0.x, m1.x, m0.y, m1.y);
            *(float4*)(b + c0 + 2) = make_float4(m0.z, m1.z, m0.w, m1.w);
        }
        __syncwarp();

#pragma unroll 2
        for (int k4 = 0; k4 < 32; k4++) {
            ulonglong2 ap0[NP_L], ap1[NP_L];
#pragma unroll
            for (int rp = 0; rp < NP_L; rp++) {
                const float2* b = st + rp * 128 + 4 * k4;
                ap0[rp] = *(const ulonglong2*)(b);
                ap1[rp] = *(const ulonglong2*)(b + 2);
            }
#pragma unroll
            for (int j = 0; j < 4; j++) {
                float4 w = *(const float4*)(Ws + (4 * k4 + j) * H + c0);
                u64 wa = pk2(w.x, w.x), wb = pk2(w.y, w.y);
                u64 wc = pk2(w.z, w.z), wd = pk2(w.w, w.w);
#pragma unroll
                for (int rp = 0; rp < NP_L; rp++) {
                    u64 a = (j == 0) ? ap0[rp].x : (j == 1) ? ap0[rp].y
                                                 : (j == 2) ? ap1[rp].x : ap1[rp].y;
                    fma2(acc[rp][0], wa, a);
                    fma2(acc[rp][1], wb, a);
                    fma2(acc[rp][2], wc, a);
                    fma2(acc[rp][3], wd, a);
                }
            }
        }
        __syncwarp();

        // ======== phase B: x @ Wr (k = 128..255), same stage buffer ========
#pragma unroll
        for (int rp = 0; rp < NP_L; rp++) {
            int r0 = base + 2 * rp, r1 = r0 + 1;
            float4 x0 = make_float4(0.f, 0.f, 0.f, 0.f), x1 = x0;
            if (r0 < n) x0 = *(const float4*)(x + (size_t)r0 * H + c0);
            if (r1 < n) x1 = *(const float4*)(x + (size_t)r1 * H + c0);
            float2* b = st + rp * 128;
            *(float4*)(b + c0) = make_float4(x0.x, x1.x, x0.y, x1.y);
            *(float4*)(b + c0 + 2) = make_float4(x0.z, x1.z, x0.w, x1.w);
        }
        __syncwarp();

#pragma unroll 2
        for (int k4 = 0; k4 < 32; k4++) {
            ulonglong2 ap0[NP_L], ap1[NP_L];
#pragma unroll
            for (int rp = 0; rp < NP_L; rp++) {
                const float2* b = st + rp * 128 + 4 * k4;
                ap0[rp] = *(const ulonglong2*)(b);
                ap1[rp] = *(const ulonglong2*)(b + 2);
            }
#pragma unroll
            for (int j = 0; j < 4; j++) {
                float4 w = *(const float4*)(Ws + (128 + 4 * k4 + j) * H + c0);
                u64 wa = pk2(w.x, w.x), wb = pk2(w.y, w.y);
                u64 wc = pk2(w.z, w.z), wd = pk2(w.w, w.w);
#pragma unroll
                for (int rp = 0; rp < NP_L; rp++) {
                    u64 a = (j == 0) ? ap0[rp].x : (j == 1) ? ap0[rp].y
                                                 : (j == 2) ? ap1[rp].x : ap1[rp].y;
                    fma2(acc[rp][0], wa, a);
                    fma2(acc[rp][1], wb, a);
                    fma2(acc[rp][2], wc, a);
                    fma2(acc[rp][3], wd, a);
                }
            }
        }

        // ======== epilogue ========
#pragma unroll
        for (int rp = 0; rp < NP_L; rp++) {
            int r0 = base + 2 * rp, r1 = r0 + 1;
            float2 v0 = upk(acc[rp][0]), v1 = upk(acc[rp][1]);
            float2 v2 = upk(acc[rp][2]), v3 = upk(acc[rp][3]);
            if (r0 < n)
                *(float4*)(out + (size_t)r0 * H + c0) =
                    make_float4(fmaxf(v0.x + b4.x, 0.f), fmaxf(v1.x + b4.y, 0.f),
                                fmaxf(v2.x + b4.z, 0.f), fmaxf(v3.x + b4.w, 0.f));
            if (r1 < n)
                *(float4*)(out + (size_t)r1 * H + c0) =
                    make_float4(fmaxf(v0.y + b4.x, 0.f), fmaxf(v1.y + b4.y, 0.f),
                                fmaxf(v2.y + b4.z, 0.f), fmaxf(v3.y + b4.w, 0.f));
        }
        __syncwarp();
    }
}

// ---------------- u/v precompute (unchanged NP=4 body + dynamic warp-tiles) ----------------
__global__ void __launch_bounds__(TPB, 1)
uv_kernel(const float* __restrict__ x, const float* __restrict__ W1, float* __restrict__ u,
          float* __restrict__ v, int* ctr, int n) {
    extern __shared__ float sm[];
    float* Ws = sm;                           // full W1: 256*128 floats = 128KB
    float2* stage = (float2*)(sm + 256 * H);  // WARPS * NP_UV * 128 float2 = 48KB
    for (int i = threadIdx.x; i < 256 * H; i += TPB) Ws[i] = W1[i];
    __syncthreads();
    const int warp = threadIdx.x >> 5, lane = threadIdx.x & 31;
    const int c0 = lane * 4;
    float2* st = stage + warp * (NP_UV * 128);
    const int ntiles = (n + RPUV - 1) / RPUV;

    for (;;) {
        int t = next_tile(ctr, lane);
        if (t >= ntiles) break;
        int base = t * RPUV;
#pragma unroll
        for (int rp = 0; rp < NP_UV; rp++) {
            int r0 = base + 2 * rp, r1 = r0 + 1;
            float4 x0 = make_float4(0.f, 0.f, 0.f, 0.f), x1 = x0;
            if (r0 < n) x0 = *(const float4*)(x + (size_t)r0 * H + c0);
            if (r1 < n) x1 = *(const float4*)(x + (size_t)r1 * H + c0);
            float2* b = st + rp * 128;
            *(float4*)(b + c0) = make_float4(x0.x, x1.x, x0.y, x1.y);
            *(float4*)(b + c0 + 2) = make_float4(x0.z, x1.z, x0.w, x1.w);
        }
        __syncwarp();

        u64 au[NP_UV][4], av[NP_UV][4];
#pragma unroll
        for (int rp = 0; rp < NP_UV; rp++)
#pragma unroll
            for (int c = 0; c < 4; c++) { au[rp][c] = 0ull; av[rp][c] = 0ull; }

#pragma unroll 2
        for (int k4 = 0; k4 < 32; k4++) {
            ulonglong2 ap0[NP_UV], ap1[NP_UV];
#pragma unroll
            for (int rp = 0; rp < NP_UV; rp++) {
                const float2* b = st + rp * 128 + 4 * k4;
                ap0[rp] = *(const ulonglong2*)(b);
                ap1[rp] = *(const ulonglong2*)(b + 2);
            }
#pragma unroll
            for (int j = 0; j < 4; j++) {
                int k = 4 * k4 + j;
                float4 wu = *(const float4*)(Ws + k * H + c0);
                float4 wv = *(const float4*)(Ws + (128 + k) * H + c0);
                u64 ua = pk2(wu.x, wu.x), ub = pk2(wu.y, wu.y);
                u64 uc = pk2(wu.z, wu.z), ud = pk2(wu.w, wu.w);
                u64 va = pk2(wv.x, wv.x), vb = pk2(wv.y, wv.y);
                u64 vc = pk2(wv.z, wv.z), vd = pk2(wv.w, wv.w);
#pragma unroll
                for (int rp = 0; rp < NP_UV; rp++) {
                    u64 a = (j == 0) ? ap0[rp].x : (j == 1) ? ap0[rp].y
                                                 : (j == 2) ? ap1[rp].x : ap1[rp].y;
                    fma2(au[rp][0], ua, a);
                    fma2(au[rp][1], ub, a);
                    fma2(au[rp][2], uc, a);
                    fma2(au[rp][3], ud, a);
                    fma2(av[rp][0], va, a);
                    fma2(av[rp][1], vb, a);
                    fma2(av[rp][2], vc, a);
                    fma2(av[rp][3], vd, a);
                }
            }
        }

#pragma unroll
        for (int rp = 0; rp < NP_UV; rp++) {
            int r0 = base + 2 * rp, r1 = r0 + 1;
            float2 a0 = upk(au[rp][0]), a1 = upk(au[rp][1]), a2 = upk(au[rp][2]),
                   a3 = upk(au[rp][3]);
            float2 b0 = upk(av[rp][0]), b1 = upk(av[rp][1]), b2 = upk(av[rp][2]),
                   b3 = upk(av[rp][3]);
            if (r0 < n) {
                *(float4*)(u + (size_t)r0 * H + c0) = make_float4(a0.x, a1.x, a2.x, a3.x);
                *(float4*)(v + (size_t)r0 * H + c0) = make_float4(b0.x, b1.x, b2.x, b3.x);
            }
            if (r1 < n) {
                *(float4*)(u + (size_t)r1 * H + c0) = make_float4(a0.y, a1.y, a2.y, a3.y);
                *(float4*)(v + (size_t)r1 * H + c0) = make_float4(b0.y, b1.y, b2.y, b3.y);
            }
        }
        __syncwarp();
    }
}

// ---------------- edge classifier: logits = relu(u[s]+v[d]+b1) @ W2 + b2 ----------------
__global__ void edge_kernel(const float* __restrict__ u, const float* __restrict__ v,
                            const int* __restrict__ qs, const int* __restrict__ qd,
                            const float* __restrict__ b1, const float* __restrict__ W2,
                            const float* __restrict__ b2, float* __restrict__ out, int nq) {
    __shared__ float W2s[H * 8];
    __shared__ float b1s[H];
    __shared__ float b2s[8];
    for (int i = threadIdx.x; i < H * 8; i += blockDim.x) W2s[i] = W2[i];
    for (int i = threadIdx.x; i < H; i += blockDim.x) b1s[i] = b1[i];
    if (threadIdx.x < 8) b2s[threadIdx.x] = b2[threadIdx.x];
    __syncthreads();

    int idx = blockIdx.x * blockDim.x + threadIdx.x;
    int stride = gridDim.x * blockDim.x;
    for (int e = idx; e < nq; e += stride) {
        size_t s = (size_t)qs[e];
        size_t d = (size_t)qd[e];
        const float4* ur = (const float4*)(u + s * H);
        const float4* vr = (const float4*)(v + d * H);
        float lg[8];
#pragma unroll
        for (int c = 0; c < 8; c++) lg[c] = b2s[c];
#pragma unroll 8
        for (int k4 = 0; k4 < 32; k4++) {
            float4 a = __ldg(ur + k4);
            float4 b = __ldg(vr + k4);
            float h0 = fmaxf(a.x + b.x + b1s[k4 * 4 + 0], 0.f);
            float h1 = fmaxf(a.y + b.y + b1s[k4 * 4 + 1], 0.f);
            float h2 = fmaxf(a.z + b.z + b1s[k4 * 4 + 2], 0.f);
            float h3 = fmaxf(a.w + b.w + b1s[k4 * 4 + 3], 0.f);
#pragma unroll
            for (int c = 0; c < 8; c++) {
                lg[c] += h0 * W2s[(k4 * 4 + 0) * 8 + c];
                lg[c] += h1 * W2s[(k4 * 4 + 1) * 8 + c];
                lg[c] += h2 * W2s[(k4 * 4 + 2) * 8 + c];
                lg[c] += h3 * W2s[(k4 * 4 + 3) * 8 + c];
            }
        }
        float4* op = (float4*)(out + (size_t)e * 8);
        op[0] = make_float4(lg[0], lg[1], lg[2], lg[3]);
        op[1] = make_float4(lg[4], lg[5], lg[6], lg[7]);
    }
}

// ---------------- host ----------------
#define SMEM_LAYER (256 * H * 4 + WARPS * NP_L * 128 * 8)  // 128KB + 72KB = 200KB
#define SMEM_UV (256 * H * 4 + WARPS * NP_UV * 128 * 8)    // 128KB + 48KB = 176KB

extern "C" void kernel_launch(void* const* d_in, const int* in_sizes, int n_in, void* d_out,
                              int out_size) {
    const float* node_emb = (const float*)d_in[0];
    const float* Wl0 = (const float*)d_in[1];
    const float* bl0 = (const float*)d_in[2];
    const float* Wr0 = (const float*)d_in[3];
    const float* Wl1 = (const float*)d_in[4];
    const float* bl1 = (const float*)d_in[5];
    const float* Wr1 = (const float*)d_in[6];
    const float* mW1 = (const float*)d_in[7];
    const float* mb1 = (const float*)d_in[8];
    const float* mW2 = (const float*)d_in[9];
    const float* mb2 = (const float*)d_in[10];
    const int* eidx = (const int*)d_in[11];  // int32 (JAX x64 disabled)
    const int* eq = (const int*)d_in[12];    // int32

    const int n = in_sizes[0] / H;    // 100000
    const int nE = in_sizes[11] / 2;  // 1600000
    const int nq = in_sizes[12] / 2;  // 500000

    float *mean, *x1, *x2, *u, *v;
    int *cnt, *off, *cur, *bsum, *csr, *ctr;
    cudaGetSymbolAddress((void**)&mean, g_mean);
    cudaGetSymbolAddress((void**)&x1, g_x1);
    cudaGetSymbolAddress((void**)&x2, g_x2);
    cudaGetSymbolAddress((void**)&u, g_u);
    cudaGetSymbolAddress((void**)&v, g_v);
    cudaGetSymbolAddress((void**)&cnt, g_cnt);
    cudaGetSymbolAddress((void**)&off, g_off);
    cudaGetSymbolAddress((void**)&cur, g_cur);
    cudaGetSymbolAddress((void**)&bsum, g_bsum);
    cudaGetSymbolAddress((void**)&csr, g_csr);
    cudaGetSymbolAddress((void**)&ctr, g_ctr);

    int sms = 148;
    cudaDeviceGetAttribute(&sms, cudaDevAttrMultiProcessorCount, 0);
    cudaFuncSetAttribute(layer_kernel, cudaFuncAttributeMaxDynamicSharedMemorySize, SMEM_LAYER);
    cudaFuncSetAttribute(uv_kernel, cudaFuncAttributeMaxDynamicSharedMemorySize, SMEM_UV);

    const int* esrc = eidx;
    const int* edst = eidx + nE;
    const int nscan = (n + 1023) / 1024;  // 98 blocks

    // ---- CSR build (once; shared by both layers) + tile-counter reset ----
    zeroi_kernel<<<(n + 255) / 256, 256>>>(cnt, n);
    zeroi_kernel<<<1, 32>>>(ctr, 4);
    hist_kernel<<<sms * 8, 256>>>(edst, cnt, nE);
    scan1_kernel<<<nscan, 1024>>>(cnt, off, bsum, n);
    scan2_kernel<<<1, 128>>>(bsum, nscan);
    scan3_kernel<<<(n + 255) / 256, 256>>>(off, bsum, cur, n, nE);
    fill_kernel<<<sms * 8, 256>>>(esrc, edst, cur, csr, nE);

    const int gather_blocks = (n * 32 + 255) / 256;

    // ---- layer 0 ----
    gather_kernel<<<gather_blocks, 256>>>(node_emb, csr, off, mean, n);
    layer_kernel<<<sms, TPB, SMEM_LAYER>>>(node_emb, mean, Wl0, Wr0, bl0, x1, ctr + 0, n);

    // ---- layer 1 ----
    gather_kernel<<<gather_blocks, 256>>>(x1, csr, off, mean, n);
    layer_kernel<<<sms, TPB, SMEM_LAYER>>>(x1, mean, Wl1, Wr1, bl1, x2, ctr + 1, n);

    // ---- edge classifier ----
    uv_kernel<<<sms, TPB, SMEM_UV>>>(x2, mW1, u, v, ctr + 2, n);
    edge_kernel<<<(nq + 255) / 256, 256>>>(u, v, eq, eq + nq, mb1, mW2, mb2, (float*)d_out, nq);
}